// round 16
// baseline (speedup 1.0000x reference)
#include <cuda_runtime.h>
#include <cuda_fp16.h>
#include <math.h>

typedef unsigned long long ull;
typedef unsigned int u32;

// Problem constants
#define BATCH 2
#define TT 2048
#define DD 2048
#define HK 16
#define HV 32
#define KD 128
#define VD 128
#define KEY_DIM 2048
#define VALUE_DIM 4096
#define QKVZ_S 12416            // 12288 qkvz cols + 64 ba cols + 64 pad
#define BT (BATCH*TT)

// ---------------------------------------------------------------------------
// Scratch
// ---------------------------------------------------------------------------
__device__ __half g_qkvzh[(size_t)BT * QKVZ_S];      // 102 MB  GEMM1 out (f16)
__device__ __half g_qnh[(size_t)BT * HK * KD];       // f16 q (l2-normed)
__device__ __half g_knh[(size_t)BT * HK * KD];       // f16 k
__device__ __half g_vh [(size_t)BT * HV * VD];       // f16 v
__device__ float g_o   [(size_t)BT * HV * VD];
__device__ float2 g_gb [(size_t)BT * HV];            // (exp(g), beta)
__device__ __half g_ah [(size_t)BT * DD];            // hs  fp16      [M,K]
__device__ __half g_w1h[(size_t)QKVZ_S * DD];        // [Wqkvz|Wba|0]^T fp16 [N,K]
__device__ __half g_w2h[(size_t)DD * VALUE_DIM];     // W_out^T fp16  [N,K]
__device__ __half g_xh [(size_t)BT * VALUE_DIM];     // rmsnorm out   [M,K]

// ---------------------------------------------------------------------------
// Helpers
// ---------------------------------------------------------------------------
__device__ __forceinline__ float silu_f(float x) {
    float t;
    asm("tanh.approx.f32 %0, %1;" : "=f"(t) : "f"(x * 0.5f));
    return 0.5f * x * (1.f + t);
}
__device__ __forceinline__ ull ffma2(ull a, ull b, ull c) {
    ull d; asm("fma.rn.f32x2 %0, %1, %2, %3;" : "=l"(d) : "l"(a), "l"(b), "l"(c));
    return d;
}
__device__ __forceinline__ ull fmul2(ull a, ull b) {
    ull d; asm("mul.rn.f32x2 %0, %1, %2;" : "=l"(d) : "l"(a), "l"(b));
    return d;
}
__device__ __forceinline__ ull pack2(float x, float y) {
    ull r; asm("mov.b64 %0, {%1, %2};" : "=l"(r) : "f"(x), "f"(y));
    return r;
}
__device__ __forceinline__ float lo2(ull a) { return __uint_as_float((u32)(a & 0xffffffffull)); }
__device__ __forceinline__ float hi2(ull a) { return __uint_as_float((u32)(a >> 32)); }
// half2 (as u32) -> packed f32x2 (ull)
__device__ __forceinline__ ull h2f2(u32 h) {
    float2 f = __half22float2(*(const __half2*)&h);
    return pack2(f.x, f.y);
}

__device__ __forceinline__ u32 cvta_smem(const void* p) {
    u32 a;
    asm("{ .reg .u64 t; cvta.to.shared.u64 t, %1; cvt.u32.u64 %0, t; }"
        : "=r"(a) : "l"(p));
    return a;
}
__device__ __forceinline__ void cp16(u32 dst, const void* src) {
    asm volatile("cp.async.cg.shared.global [%0], [%1], 16;"
                 :: "r"(dst), "l"(src) : "memory");
}
__device__ __forceinline__ void ldsm4(u32& r0, u32& r1, u32& r2, u32& r3, u32 a) {
    asm volatile("ldmatrix.sync.aligned.m8n8.x4.shared.b16 {%0,%1,%2,%3}, [%4];"
                 : "=r"(r0), "=r"(r1), "=r"(r2), "=r"(r3) : "r"(a));
}
__device__ __forceinline__ void stC(float* p, float a, float b) {
    *(float2*)p = make_float2(a, b);
}
__device__ __forceinline__ void stC(__half* p, float a, float b) {
    *(__half2*)p = __floats2half2_rn(a, b);
}

// ---------------------------------------------------------------------------
// fp16 mma.sync GEMM: C[M,N] = A[M,K](f16) * Bt[N,K](f16)^T, f32 accumulate.
// Tile 128x128x64, 256 threads, warp tile 32x64, m16n8k16, ldmatrix,
// 3-stage cp.async, 2 CTAs/SM. Row = 64 halves + 8 pad = 144 B.
// ---------------------------------------------------------------------------
#define ROWB 144
#define SB_OFF (128*ROWB)
#define STAGE_BYTES (2*128*ROWB)           // 36864
#define NSTAGES 3
#define GEMM_SMEM (NSTAGES*STAGE_BYTES)    // 110592

__device__ __forceinline__ void gemm_load_stage(
    u32 sb, const __half* __restrict__ Ag, const __half* __restrict__ Bg,
    int K, int kiter, int buf, int tid)
{
    const u32 st = sb + (u32)buf * STAGE_BYTES;
    const int k0 = kiter * 64;
#pragma unroll
    for (int j = 0; j < 4; j++) {
        int c = tid + j * 256;
        int r = c >> 3, cc = c & 7;
        cp16(st + (u32)(r * ROWB + cc * 16), Ag + (size_t)r * K + k0 + cc * 8);
    }
#pragma unroll
    for (int j = 0; j < 4; j++) {
        int c = tid + j * 256;
        int r = c >> 3, cc = c & 7;
        cp16(st + (u32)(SB_OFF + r * ROWB + cc * 16),
             Bg + (size_t)r * K + k0 + cc * 8);
    }
}

template <typename OutT>
__global__ __launch_bounds__(256, 2) void h_gemm_kernel(
    const __half* __restrict__ A, const __half* __restrict__ Bt,
    OutT* __restrict__ C, int M, int N, int K)
{
    extern __shared__ __align__(16) char smem[];
    const u32 sb = cvta_smem(smem);
    const int tid = threadIdx.x;
    const int bx = blockIdx.x;
    const int by = blockIdx.y;
    const int warp = tid >> 5;
    const int lane = tid & 31;
    const int g = lane >> 2;
    const int tg = lane & 3;
    const int warp_m = warp >> 1;
    const int warp_n = warp & 1;
    const int niters = K >> 6;

    const u32 a_base = sb +
        (u32)((warp_m * 32 + (lane & 15)) * ROWB + ((lane >> 4) << 4));
    const u32 b_base = sb + SB_OFF +
        (u32)((warp_n * 64 + (lane & 15)) * ROWB + ((lane >> 4) << 4));

    const __half* Ag = A + (size_t)(by * 128) * K;
    const __half* Bg = Bt + (size_t)(bx * 128) * K;

    float acc[2][8][4];
#pragma unroll
    for (int mt = 0; mt < 2; mt++)
#pragma unroll
        for (int nt = 0; nt < 8; nt++)
#pragma unroll
            for (int r = 0; r < 4; r++) acc[mt][nt][r] = 0.f;

#pragma unroll
    for (int s = 0; s < NSTAGES - 1; s++) {
        gemm_load_stage(sb, Ag, Bg, K, s, s, tid);
        asm volatile("cp.async.commit_group;" ::: "memory");
    }

    int buf = 0;
    for (int i = 0; i < niters; i++) {
        asm volatile("cp.async.wait_group %0;" :: "n"(NSTAGES - 2) : "memory");
        __syncthreads();

        if (i + NSTAGES - 1 < niters) {
            int nb = buf + NSTAGES - 1; if (nb >= NSTAGES) nb -= NSTAGES;
            gemm_load_stage(sb, Ag, Bg, K, i + NSTAGES - 1, nb, tid);
        }
        asm volatile("cp.async.commit_group;" ::: "memory");

        const u32 ab = a_base + (u32)buf * STAGE_BYTES;
        const u32 bb = b_base + (u32)buf * STAGE_BYTES;
#pragma unroll
        for (int ks = 0; ks < 4; ks++) {
            u32 af[2][4];
#pragma unroll
            for (int mt = 0; mt < 2; mt++)
                ldsm4(af[mt][0], af[mt][1], af[mt][2], af[mt][3],
                      ab + (u32)(mt * 16 * ROWB + ks * 32));
            u32 bf[8][2];
#pragma unroll
            for (int p = 0; p < 4; p++) {
                u32 m0, m1, m2, m3;
                ldsm4(m0, m1, m2, m3, bb + (u32)(p * 16 * ROWB + ks * 32));
                bf[2 * p][0] = m0;     bf[2 * p][1] = m2;
                bf[2 * p + 1][0] = m1; bf[2 * p + 1][1] = m3;
            }
#pragma unroll
            for (int mt = 0; mt < 2; mt++)
#pragma unroll
                for (int nt = 0; nt < 8; nt++) {
                    asm volatile(
                        "mma.sync.aligned.m16n8k16.row.col.f32.f16.f16.f32 "
                        "{%0,%1,%2,%3}, {%4,%5,%6,%7}, {%8,%9}, {%0,%1,%2,%3};\n"
                        : "+f"(acc[mt][nt][0]), "+f"(acc[mt][nt][1]),
                          "+f"(acc[mt][nt][2]), "+f"(acc[mt][nt][3])
                        : "r"(af[mt][0]), "r"(af[mt][1]),
                          "r"(af[mt][2]), "r"(af[mt][3]),
                          "r"(bf[nt][0]), "r"(bf[nt][1]));
                }
        }
        buf++; if (buf >= NSTAGES) buf = 0;
    }

#pragma unroll
    for (int mt = 0; mt < 2; mt++) {
        int row = by * 128 + warp_m * 32 + mt * 16 + g;
#pragma unroll
        for (int nt = 0; nt < 8; nt++) {
            int col = bx * 128 + warp_n * 64 + nt * 8 + tg * 2;
            stC(C + (size_t)row * N + col, acc[mt][nt][0], acc[mt][nt][1]);
            stC(C + (size_t)(row + 8) * N + col, acc[mt][nt][2], acc[mt][nt][3]);
        }
    }
}

// ---------------------------------------------------------------------------
// Prep kernels
// ---------------------------------------------------------------------------
__global__ __launch_bounds__(256) void convert_h_kernel(
    const float* __restrict__ in, __half* __restrict__ out, int n4)
{
    int i = blockIdx.x * 256 + threadIdx.x;
    if (i < n4) {
        float4 v = ((const float4*)in)[i];
        ((__half2*)out)[2 * i] = __floats2half2_rn(v.x, v.y);
        ((__half2*)out)[2 * i + 1] = __floats2half2_rn(v.z, v.w);
    }
}

__global__ __launch_bounds__(256) void transpose_h_kernel(
    const float* __restrict__ src, __half* __restrict__ dst, int R, int C)
{
    __shared__ float t[32][33];
    const int bx = blockIdx.x * 32;
    const int by = blockIdx.y * 32;
    const int tx = threadIdx.x & 31;
    const int ty = threadIdx.x >> 5;
#pragma unroll
    for (int j = 0; j < 32; j += 8)
        t[ty + j][tx] = src[(size_t)(by + ty + j) * C + bx + tx];
    __syncthreads();
#pragma unroll
    for (int j = 0; j < 32; j += 8)
        dst[(size_t)(bx + ty + j) * R + by + tx] = __float2half(t[tx][ty + j]);
}

__global__ __launch_bounds__(256) void transpose_ba_kernel(
    const float* __restrict__ src, __half* __restrict__ w1h)
{
    __shared__ float t[32][33];
    const int bx = blockIdx.x * 32;
    const int by = blockIdx.y * 32;
    const int tx = threadIdx.x & 31;
    const int ty = threadIdx.x >> 5;
#pragma unroll
    for (int j = 0; j < 32; j += 8) {
        float v = 0.f;
        if (bx + tx < 64) v = src[(size_t)(by + ty + j) * 64 + bx + tx];
        t[ty + j][tx] = v;
    }
    __syncthreads();
#pragma unroll
    for (int j = 0; j < 32; j += 8)
        w1h[(size_t)(12288 + bx + ty + j) * DD + by + tx] =
            __float2half(t[tx][ty + j]);
}

// ---------------------------------------------------------------------------
// conv + silu + l2norm + gating -> f16 qn/kn/vv outputs, (exp(g),beta) pairs
// ---------------------------------------------------------------------------
__global__ __launch_bounds__(256) void conv_gate_kernel(
    const __half* __restrict__ qkvz,
    const float* __restrict__ convw, const float* __restrict__ Alog,
    const float* __restrict__ dtb,
    __half* __restrict__ qn, __half* __restrict__ kn, __half* __restrict__ vv,
    float2* __restrict__ gb)
{
    const int bt = blockIdx.x;
    const int b = bt / TT;
    const int t = bt % TT;
    const int tid = threadIdx.x;
    __shared__ float buf[2 * KEY_DIM];
    __shared__ float rnorm[2 * HK];

#pragma unroll
    for (int it = 0; it < 8; it++) {
        int c2 = tid * 2 + it * 512;
        float4 w0 = *(const float4*)(convw + c2 * 4);
        float4 w1 = *(const float4*)(convw + c2 * 4 + 4);
        float wa0[4] = {w0.x, w0.y, w0.z, w0.w};
        float wa1[4] = {w1.x, w1.y, w1.z, w1.w};
        float a0 = 0.f, a1 = 0.f;
#pragma unroll
        for (int j = 0; j < 4; j++) {
            int ts = t - 3 + j;
            if (ts >= 0) {
                __half2 hv = *(const __half2*)(qkvz +
                    ((size_t)b * TT + ts) * QKVZ_S + c2);
                float2 f = __half22float2(hv);
                a0 += wa0[j] * f.x;
                a1 += wa1[j] * f.y;
            }
        }
        buf[c2] = silu_f(a0);
        buf[c2 + 1] = silu_f(a1);
    }
    __syncthreads();

    const int warp = tid >> 5;
    const int lane = tid & 31;
    for (int gi = warp; gi < 32; gi += 8) {
        float s = 0.f;
#pragma unroll
        for (int l = 0; l < 4; l++) {
            float x = buf[gi * 128 + lane + 32 * l];
            s += x * x;
        }
#pragma unroll
        for (int off = 16; off; off >>= 1)
            s += __shfl_xor_sync(0xffffffffu, s, off);
        if (lane == 0) rnorm[gi] = rsqrtf(s + 1e-6f);
    }
    __syncthreads();

    const float QSCALE = 0.08838834764831845f;
    for (int i = tid; i < KEY_DIM; i += 256) {
        int kh = i >> 7;
        int d  = i & 127;
        size_t o0 = ((size_t)bt * HK + kh) * KD + d;
        qn[o0] = __float2half(buf[i] * rnorm[kh] * QSCALE);
        kn[o0] = __float2half(buf[KEY_DIM + i] * rnorm[HK + kh]);
    }

#pragma unroll
    for (int it = 0; it < 8; it++) {
        int c2 = 2 * KEY_DIM + tid * 2 + it * 512;
        float4 w0 = *(const float4*)(convw + c2 * 4);
        float4 w1 = *(const float4*)(convw + c2 * 4 + 4);
        float wa0[4] = {w0.x, w0.y, w0.z, w0.w};
        float wa1[4] = {w1.x, w1.y, w1.z, w1.w};
        float a0 = 0.f, a1 = 0.f;
#pragma unroll
        for (int j = 0; j < 4; j++) {
            int ts = t - 3 + j;
            if (ts >= 0) {
                __half2 hv = *(const __half2*)(qkvz +
                    ((size_t)b * TT + ts) * QKVZ_S + c2);
                float2 f = __half22float2(hv);
                a0 += wa0[j] * f.x;
                a1 += wa1[j] * f.y;
            }
        }
        int cv = c2 - 2 * KEY_DIM;
        *(__half2*)(vv + (size_t)bt * VALUE_DIM + cv) =
            __floats2half2_rn(silu_f(a0), silu_f(a1));
    }

    if (tid < HV) {
        float bg = __half2float(qkvz[(size_t)bt * QKVZ_S + 12288 + tid]);
        float a  = __half2float(qkvz[(size_t)bt * QKVZ_S + 12320 + tid]) + dtb[tid];
        float beta = 1.f / (1.f + __expf(-bg));
        float sp = (a > 20.f) ? a : log1pf(__expf(a));
        float eg = __expf(-__expf(Alog[tid]) * sp);
        gb[(size_t)bt * HV + tid] = make_float2(eg, beta);
    }
}

// ---------------------------------------------------------------------------
// Gated delta-rule scan v7: f16 q/k/v inputs, warp-autonomous, 16 warps.
// 128 blocks = (b, h, vhalf); 512 threads. Thread tile 16k x 1v.
// Per buffer: k = 2 x uint4 (16 f16 = 32 B), q same, v = 1 f16.
// Unpack to f32x2 at step time (alu pipe); fma work unchanged.
// ---------------------------------------------------------------------------
struct ScanPB {
    uint4 k[2];
    uint4 q[2];
    float v;
    float eg, beta;
};

__device__ __forceinline__ void scan_pf(
    ScanPB& pb, int t, int b, int kh, int h, int kgofs, int vofs,
    const __half* __restrict__ qn, const __half* __restrict__ kn,
    const __half* __restrict__ vv, const float2* __restrict__ gb)
{
    int tc = t < TT ? t : TT - 1;
    size_t rowk = (((size_t)b * TT + tc) * HK + kh) * (size_t)KD + kgofs;
    const uint4* kp = (const uint4*)(kn + rowk);
    const uint4* qp = (const uint4*)(qn + rowk);
    pb.k[0] = kp[0]; pb.k[1] = kp[1];
    pb.q[0] = qp[0]; pb.q[1] = qp[1];
    size_t rowv = (((size_t)b * TT + tc) * HV + h) * (size_t)VD + vofs;
    pb.v = __half2float(vv[rowv]);
    float2 g2 = gb[((size_t)b * TT + tc) * HV + h];
    pb.eg = g2.x;
    pb.beta = g2.y;
}

__device__ __forceinline__ void scan_step(
    ull* __restrict__ S2, const ScanPB& pb, int t, int kg, size_t obase,
    float* __restrict__ oo)
{
    // unpack f16 -> packed f32x2
    const u32* kr = (const u32*)pb.k;
    const u32* qr = (const u32*)pb.q;
    ull kp[8], qp[8];
#pragma unroll
    for (int i = 0; i < 8; i++) { kp[i] = h2f2(kr[i]); qp[i] = h2f2(qr[i]); }

    ull eg2 = pack2(pb.eg, pb.eg);
    ull p2a = 0ull, p2b = 0ull;
#pragma unroll
    for (int m = 0; m < 4; m++) {
        ull s0 = fmul2(S2[2 * m], eg2);
        S2[2 * m] = s0;
        p2a = ffma2(kp[2 * m], s0, p2a);
        ull s1 = fmul2(S2[2 * m + 1], eg2);
        S2[2 * m + 1] = s1;
        p2b = ffma2(kp[2 * m + 1], s1, p2b);
    }
    float p = (lo2(p2a) + hi2(p2a)) + (lo2(p2b) + hi2(p2b));
    p += __shfl_xor_sync(0xffffffffu, p, 4);
    p += __shfl_xor_sync(0xffffffffu, p, 8);
    p += __shfl_xor_sync(0xffffffffu, p, 16);
    float d = (pb.v - p) * pb.beta;
    ull d2 = pack2(d, d);
    ull o2a = 0ull, o2b = 0ull;
#pragma unroll
    for (int m = 0; m < 4; m++) {
        ull s0 = ffma2(kp[2 * m], d2, S2[2 * m]);
        S2[2 * m] = s0;
        o2a = ffma2(qp[2 * m], s0, o2a);
        ull s1 = ffma2(kp[2 * m + 1], d2, S2[2 * m + 1]);
        S2[2 * m + 1] = s1;
        o2b = ffma2(qp[2 * m + 1], s1, o2b);
    }
    float o = (lo2(o2a) + hi2(o2a)) + (lo2(o2b) + hi2(o2b));
    o += __shfl_xor_sync(0xffffffffu, o, 4);
    o += __shfl_xor_sync(0xffffffffu, o, 8);
    o += __shfl_xor_sync(0xffffffffu, o, 16);
    if (kg == 0 && t < TT)
        oo[obase + (size_t)t * (HV * VD)] = o;
}

__global__ __launch_bounds__(512, 1) void scan_kernel(
    const __half* __restrict__ qn, const __half* __restrict__ kn,
    const __half* __restrict__ vv, const float2* __restrict__ gb,
    float* __restrict__ oo)
{
    const int bh2 = blockIdx.x;
    const int b = bh2 >> 6;
    const int rem = bh2 & 63;
    const int h = rem >> 1;
    const int vhalf = rem & 1;
    const int kh = h >> 1;
    const int tid = threadIdx.x;
    const int w = tid >> 5;
    const int lane = tid & 31;
    const int kg = lane >> 2;
    const int c = lane & 3;
    const int kgofs = kg * 16;
    const int vofs = vhalf * 64 + w * 4 + c;

    ull S2[8];
#pragma unroll
    for (int i = 0; i < 8; i++) S2[i] = 0ull;

    const size_t obase = (((size_t)b * TT) * HV + h) * (size_t)VD + vofs;

    ScanPB A, B;
    scan_pf(A, 0, b, kh, h, kgofs, vofs, qn, kn, vv, gb);

    for (int t = 0; t < TT; t += 2) {
        scan_pf(B, t + 1, b, kh, h, kgofs, vofs, qn, kn, vv, gb);
        scan_step(S2, A, t, kg, obase, oo);
        scan_pf(A, t + 2, b, kh, h, kgofs, vofs, qn, kn, vv, gb);
        scan_step(S2, B, t + 1, kg, obase, oo);
    }
}

// ---------------------------------------------------------------------------
// gated rmsnorm -> f16 output for GEMM2's A operand (z from f16 qkvz)
// ---------------------------------------------------------------------------
__global__ __launch_bounds__(256) void rmsnorm_kernel(
    const float* __restrict__ oo, const __half* __restrict__ qkvz,
    const float* __restrict__ nw, __half* __restrict__ xout)
{
    const int bt = blockIdx.x;
    const int warp = threadIdx.x >> 5;
    const int lane = threadIdx.x & 31;

    for (int hh = warp; hh < HV; hh += 8) {
        const size_t base = ((size_t)bt * HV + hh) * (size_t)VD;
        const __half* zz = qkvz + (size_t)bt * QKVZ_S + 2 * KEY_DIM + VALUE_DIM
                           + (size_t)hh * VD;
        float xv[4];
        float ss = 0.f;
#pragma unroll
        for (int i = 0; i < 4; i++) {
            int d = lane + 32 * i;
            float z = __half2float(zz[d]);
            float x = oo[base + d] * silu_f(z);
            xv[i] = x;
            ss += x * x;
        }
#pragma unroll
        for (int off = 16; off; off >>= 1)
            ss += __shfl_xor_sync(0xffffffffu, ss, off);
        float r = rsqrtf(ss * (1.f / 128.f) + 1e-6f);
#pragma unroll
        for (int i = 0; i < 4; i++) {
            int d = lane + 32 * i;
            xout[(size_t)bt * VALUE_DIM + hh * VD + d] =
                __float2half(xv[i] * r * (1.f + nw[d]));
        }
    }
}

// ---------------------------------------------------------------------------
// Launch
// ---------------------------------------------------------------------------
extern "C" void kernel_launch(void* const* d_in, const int* in_sizes, int n_in,
                              void* d_out, int out_size)
{
    const float* hs    = (const float*)d_in[0];
    const float* Wqkvz = (const float*)d_in[1];
    const float* Wba   = (const float*)d_in[2];
    const float* convw = (const float*)d_in[3];
    const float* Alog  = (const float*)d_in[4];
    const float* dtb   = (const float*)d_in[5];
    const float* nw    = (const float*)d_in[6];
    const float* Wout  = (const float*)d_in[7];
    float* out = (float*)d_out;

    float *oo;
    float2 *gb;
    __half *qkvzh, *qnh, *knh, *vvh, *ah, *w1h, *w2h, *xh;
    cudaGetSymbolAddress((void**)&qkvzh, g_qkvzh);
    cudaGetSymbolAddress((void**)&qnh,  g_qnh);
    cudaGetSymbolAddress((void**)&knh,  g_knh);
    cudaGetSymbolAddress((void**)&vvh,  g_vh);
    cudaGetSymbolAddress((void**)&oo,   g_o);
    cudaGetSymbolAddress((void**)&gb,   g_gb);
    cudaGetSymbolAddress((void**)&ah,   g_ah);
    cudaGetSymbolAddress((void**)&w1h,  g_w1h);
    cudaGetSymbolAddress((void**)&w2h,  g_w2h);
    cudaGetSymbolAddress((void**)&xh,   g_xh);

    cudaFuncSetAttribute(h_gemm_kernel<__half>,
                         cudaFuncAttributeMaxDynamicSharedMemorySize, GEMM_SMEM);
    cudaFuncSetAttribute(h_gemm_kernel<float>,
                         cudaFuncAttributeMaxDynamicSharedMemorySize, GEMM_SMEM);

    // prep
    convert_h_kernel<<<(BT * DD / 4 + 255) / 256, 256>>>(hs, ah, BT * DD / 4);
    transpose_h_kernel<<<dim3(12288 / 32, DD / 32), 256>>>(Wqkvz, w1h, DD, 12288);
    transpose_ba_kernel<<<dim3(4, 64), 256>>>(Wba, w1h);
    transpose_h_kernel<<<dim3(DD / 32, VALUE_DIM / 32), 256>>>(Wout, w2h, VALUE_DIM, DD);

    // 1) [qkvz | ba] = hs @ [W_qkvz | W_ba | 0]  : [4096,2048]x[2048,12416]
    h_gemm_kernel<__half><<<dim3(QKVZ_S / 128, BT / 128), 256, GEMM_SMEM>>>(
        ah, w1h, qkvzh, BT, QKVZ_S, DD);

    // 2) conv + silu + l2norm + gating (f16 outputs)
    conv_gate_kernel<<<BT, 256>>>(qkvzh, convw, Alog, dtb, qnh, knh, vvh, gb);

    // 3) gated delta rule scan (f16 inputs, 16 warps/block)
    scan_kernel<<<128, 512>>>(qnh, knh, vvh, gb, oo);

    // 4) gated rmsnorm -> f16
    rmsnorm_kernel<<<BT, 256>>>(oo, qkvzh, nw, xh);

    // 5) out = x @ W_out : [4096,4096]x[4096,2048]
    h_gemm_kernel<float><<<dim3(DD / 128, BT / 128), 256, GEMM_SMEM>>>(
        xh, w2h, out, BT, DD, VALUE_DIM);
}

// round 17
// speedup vs baseline: 1.1855x; 1.1855x over previous
#include <cuda_runtime.h>
#include <cuda_fp16.h>
#include <math.h>

typedef unsigned long long ull;
typedef unsigned int u32;

// Problem constants
#define BATCH 2
#define TT 2048
#define DD 2048
#define HK 16
#define HV 32
#define KD 128
#define VD 128
#define KEY_DIM 2048
#define VALUE_DIM 4096
#define QKVZ_S 12416            // 12288 qkvz cols + 64 ba cols + 64 pad
#define BT (BATCH*TT)

// ---------------------------------------------------------------------------
// Scratch
// ---------------------------------------------------------------------------
__device__ __half g_qkvzh[(size_t)BT * QKVZ_S];      // 102 MB  GEMM1 out (f16)
__device__ float g_qn  [(size_t)BT * HK * KD];
__device__ float g_kn  [(size_t)BT * HK * KD];
__device__ float g_v   [(size_t)BT * HV * VD];
__device__ __half g_oh [(size_t)BT * HV * VD];       // scan out, f16
__device__ float2 g_gb [(size_t)BT * HV];            // (exp(g), beta)
__device__ __half g_ah [(size_t)BT * DD];            // hs  fp16      [M,K]
__device__ __half g_w1h[(size_t)QKVZ_S * DD];        // [Wqkvz|Wba|0]^T fp16 [N,K]
__device__ __half g_w2h[(size_t)DD * VALUE_DIM];     // W_out^T fp16  [N,K]
__device__ __half g_xh [(size_t)BT * VALUE_DIM];     // rmsnorm out   [M,K]

// ---------------------------------------------------------------------------
// Helpers
// ---------------------------------------------------------------------------
__device__ __forceinline__ float silu_f(float x) {
    float t;
    asm("tanh.approx.f32 %0, %1;" : "=f"(t) : "f"(x * 0.5f));
    return 0.5f * x * (1.f + t);
}
__device__ __forceinline__ ull ffma2(ull a, ull b, ull c) {
    ull d; asm("fma.rn.f32x2 %0, %1, %2, %3;" : "=l"(d) : "l"(a), "l"(b), "l"(c));
    return d;
}
__device__ __forceinline__ ull fmul2(ull a, ull b) {
    ull d; asm("mul.rn.f32x2 %0, %1, %2;" : "=l"(d) : "l"(a), "l"(b));
    return d;
}
__device__ __forceinline__ ull pack2(float x, float y) {
    ull r; asm("mov.b64 %0, {%1, %2};" : "=l"(r) : "f"(x), "f"(y));
    return r;
}
__device__ __forceinline__ float lo2(ull a) { return __uint_as_float((u32)(a & 0xffffffffull)); }
__device__ __forceinline__ float hi2(ull a) { return __uint_as_float((u32)(a >> 32)); }

__device__ __forceinline__ u32 cvta_smem(const void* p) {
    u32 a;
    asm("{ .reg .u64 t; cvta.to.shared.u64 t, %1; cvt.u32.u64 %0, t; }"
        : "=r"(a) : "l"(p));
    return a;
}
__device__ __forceinline__ void cp16(u32 dst, const void* src) {
    asm volatile("cp.async.cg.shared.global [%0], [%1], 16;"
                 :: "r"(dst), "l"(src) : "memory");
}
__device__ __forceinline__ void ldsm4(u32& r0, u32& r1, u32& r2, u32& r3, u32 a) {
    asm volatile("ldmatrix.sync.aligned.m8n8.x4.shared.b16 {%0,%1,%2,%3}, [%4];"
                 : "=r"(r0), "=r"(r1), "=r"(r2), "=r"(r3) : "r"(a));
}
__device__ __forceinline__ void stC(float* p, float a, float b) {
    *(float2*)p = make_float2(a, b);
}
__device__ __forceinline__ void stC(__half* p, float a, float b) {
    *(__half2*)p = __floats2half2_rn(a, b);
}

// ---------------------------------------------------------------------------
// fp16 mma.sync GEMM: C[M,N] = A[M,K](f16) * Bt[N,K](f16)^T, f32 accumulate.
// Tile 128x128x64, 256 threads, warp tile 32x64, m16n8k16, ldmatrix,
// 3-stage cp.async, 2 CTAs/SM. Row = 64 halves + 8 pad = 144 B.
// ---------------------------------------------------------------------------
#define ROWB 144
#define SB_OFF (128*ROWB)
#define STAGE_BYTES (2*128*ROWB)           // 36864
#define NSTAGES 3
#define GEMM_SMEM (NSTAGES*STAGE_BYTES)    // 110592

__device__ __forceinline__ void gemm_load_stage(
    u32 sb, const __half* __restrict__ Ag, const __half* __restrict__ Bg,
    int K, int kiter, int buf, int tid)
{
    const u32 st = sb + (u32)buf * STAGE_BYTES;
    const int k0 = kiter * 64;
#pragma unroll
    for (int j = 0; j < 4; j++) {
        int c = tid + j * 256;
        int r = c >> 3, cc = c & 7;
        cp16(st + (u32)(r * ROWB + cc * 16), Ag + (size_t)r * K + k0 + cc * 8);
    }
#pragma unroll
    for (int j = 0; j < 4; j++) {
        int c = tid + j * 256;
        int r = c >> 3, cc = c & 7;
        cp16(st + (u32)(SB_OFF + r * ROWB + cc * 16),
             Bg + (size_t)r * K + k0 + cc * 8);
    }
}

template <typename OutT>
__global__ __launch_bounds__(256, 2) void h_gemm_kernel(
    const __half* __restrict__ A, const __half* __restrict__ Bt,
    OutT* __restrict__ C, int M, int N, int K)
{
    extern __shared__ __align__(16) char smem[];
    const u32 sb = cvta_smem(smem);
    const int tid = threadIdx.x;
    const int bx = blockIdx.x;
    const int by = blockIdx.y;
    const int warp = tid >> 5;
    const int lane = tid & 31;
    const int g = lane >> 2;
    const int tg = lane & 3;
    const int warp_m = warp >> 1;
    const int warp_n = warp & 1;
    const int niters = K >> 6;

    const u32 a_base = sb +
        (u32)((warp_m * 32 + (lane & 15)) * ROWB + ((lane >> 4) << 4));
    const u32 b_base = sb + SB_OFF +
        (u32)((warp_n * 64 + (lane & 15)) * ROWB + ((lane >> 4) << 4));

    const __half* Ag = A + (size_t)(by * 128) * K;
    const __half* Bg = Bt + (size_t)(bx * 128) * K;

    float acc[2][8][4];
#pragma unroll
    for (int mt = 0; mt < 2; mt++)
#pragma unroll
        for (int nt = 0; nt < 8; nt++)
#pragma unroll
            for (int r = 0; r < 4; r++) acc[mt][nt][r] = 0.f;

#pragma unroll
    for (int s = 0; s < NSTAGES - 1; s++) {
        gemm_load_stage(sb, Ag, Bg, K, s, s, tid);
        asm volatile("cp.async.commit_group;" ::: "memory");
    }

    int buf = 0;
    for (int i = 0; i < niters; i++) {
        asm volatile("cp.async.wait_group %0;" :: "n"(NSTAGES - 2) : "memory");
        __syncthreads();

        if (i + NSTAGES - 1 < niters) {
            int nb = buf + NSTAGES - 1; if (nb >= NSTAGES) nb -= NSTAGES;
            gemm_load_stage(sb, Ag, Bg, K, i + NSTAGES - 1, nb, tid);
        }
        asm volatile("cp.async.commit_group;" ::: "memory");

        const u32 ab = a_base + (u32)buf * STAGE_BYTES;
        const u32 bb = b_base + (u32)buf * STAGE_BYTES;
#pragma unroll
        for (int ks = 0; ks < 4; ks++) {
            u32 af[2][4];
#pragma unroll
            for (int mt = 0; mt < 2; mt++)
                ldsm4(af[mt][0], af[mt][1], af[mt][2], af[mt][3],
                      ab + (u32)(mt * 16 * ROWB + ks * 32));
            u32 bf[8][2];
#pragma unroll
            for (int p = 0; p < 4; p++) {
                u32 m0, m1, m2, m3;
                ldsm4(m0, m1, m2, m3, bb + (u32)(p * 16 * ROWB + ks * 32));
                bf[2 * p][0] = m0;     bf[2 * p][1] = m2;
                bf[2 * p + 1][0] = m1; bf[2 * p + 1][1] = m3;
            }
#pragma unroll
            for (int mt = 0; mt < 2; mt++)
#pragma unroll
                for (int nt = 0; nt < 8; nt++) {
                    asm volatile(
                        "mma.sync.aligned.m16n8k16.row.col.f32.f16.f16.f32 "
                        "{%0,%1,%2,%3}, {%4,%5,%6,%7}, {%8,%9}, {%0,%1,%2,%3};\n"
                        : "+f"(acc[mt][nt][0]), "+f"(acc[mt][nt][1]),
                          "+f"(acc[mt][nt][2]), "+f"(acc[mt][nt][3])
                        : "r"(af[mt][0]), "r"(af[mt][1]),
                          "r"(af[mt][2]), "r"(af[mt][3]),
                          "r"(bf[nt][0]), "r"(bf[nt][1]));
                }
        }
        buf++; if (buf >= NSTAGES) buf = 0;
    }

#pragma unroll
    for (int mt = 0; mt < 2; mt++) {
        int row = by * 128 + warp_m * 32 + mt * 16 + g;
#pragma unroll
        for (int nt = 0; nt < 8; nt++) {
            int col = bx * 128 + warp_n * 64 + nt * 8 + tg * 2;
            stC(C + (size_t)row * N + col, acc[mt][nt][0], acc[mt][nt][1]);
            stC(C + (size_t)(row + 8) * N + col, acc[mt][nt][2], acc[mt][nt][3]);
        }
    }
}

// ---------------------------------------------------------------------------
// Prep kernels
// ---------------------------------------------------------------------------
__global__ __launch_bounds__(256) void convert_h_kernel(
    const float* __restrict__ in, __half* __restrict__ out, int n4)
{
    int i = blockIdx.x * 256 + threadIdx.x;
    if (i < n4) {
        float4 v = ((const float4*)in)[i];
        ((__half2*)out)[2 * i] = __floats2half2_rn(v.x, v.y);
        ((__half2*)out)[2 * i + 1] = __floats2half2_rn(v.z, v.w);
    }
}

__global__ __launch_bounds__(256) void transpose_h_kernel(
    const float* __restrict__ src, __half* __restrict__ dst, int R, int C)
{
    __shared__ float t[32][33];
    const int bx = blockIdx.x * 32;
    const int by = blockIdx.y * 32;
    const int tx = threadIdx.x & 31;
    const int ty = threadIdx.x >> 5;
#pragma unroll
    for (int j = 0; j < 32; j += 8)
        t[ty + j][tx] = src[(size_t)(by + ty + j) * C + bx + tx];
    __syncthreads();
#pragma unroll
    for (int j = 0; j < 32; j += 8)
        dst[(size_t)(bx + ty + j) * R + by + tx] = __float2half(t[tx][ty + j]);
}

__global__ __launch_bounds__(256) void transpose_ba_kernel(
    const float* __restrict__ src, __half* __restrict__ w1h)
{
    __shared__ float t[32][33];
    const int bx = blockIdx.x * 32;
    const int by = blockIdx.y * 32;
    const int tx = threadIdx.x & 31;
    const int ty = threadIdx.x >> 5;
#pragma unroll
    for (int j = 0; j < 32; j += 8) {
        float v = 0.f;
        if (bx + tx < 64) v = src[(size_t)(by + ty + j) * 64 + bx + tx];
        t[ty + j][tx] = v;
    }
    __syncthreads();
#pragma unroll
    for (int j = 0; j < 32; j += 8)
        w1h[(size_t)(12288 + bx + ty + j) * DD + by + tx] =
            __float2half(t[tx][ty + j]);
}

// ---------------------------------------------------------------------------
// conv + silu + l2norm + gating (qkvz f16, stride QKVZ_S; ba folded in).
// ---------------------------------------------------------------------------
__global__ __launch_bounds__(256) void conv_gate_kernel(
    const __half* __restrict__ qkvz,
    const float* __restrict__ convw, const float* __restrict__ Alog,
    const float* __restrict__ dtb,
    float* __restrict__ qn, float* __restrict__ kn, float* __restrict__ vv,
    float2* __restrict__ gb)
{
    const int bt = blockIdx.x;
    const int b = bt / TT;
    const int t = bt % TT;
    const int tid = threadIdx.x;
    __shared__ float buf[2 * KEY_DIM];
    __shared__ float rnorm[2 * HK];

#pragma unroll
    for (int it = 0; it < 8; it++) {
        int c2 = tid * 2 + it * 512;
        float4 w0 = *(const float4*)(convw + c2 * 4);
        float4 w1 = *(const float4*)(convw + c2 * 4 + 4);
        float wa0[4] = {w0.x, w0.y, w0.z, w0.w};
        float wa1[4] = {w1.x, w1.y, w1.z, w1.w};
        float a0 = 0.f, a1 = 0.f;
#pragma unroll
        for (int j = 0; j < 4; j++) {
            int ts = t - 3 + j;
            if (ts >= 0) {
                __half2 hv = *(const __half2*)(qkvz +
                    ((size_t)b * TT + ts) * QKVZ_S + c2);
                float2 f = __half22float2(hv);
                a0 += wa0[j] * f.x;
                a1 += wa1[j] * f.y;
            }
        }
        buf[c2] = silu_f(a0);
        buf[c2 + 1] = silu_f(a1);
    }
    __syncthreads();

    const int warp = tid >> 5;
    const int lane = tid & 31;
    for (int gi = warp; gi < 32; gi += 8) {
        float s = 0.f;
#pragma unroll
        for (int l = 0; l < 4; l++) {
            float x = buf[gi * 128 + lane + 32 * l];
            s += x * x;
        }
#pragma unroll
        for (int off = 16; off; off >>= 1)
            s += __shfl_xor_sync(0xffffffffu, s, off);
        if (lane == 0) rnorm[gi] = rsqrtf(s + 1e-6f);
    }
    __syncthreads();

    const float QSCALE = 0.08838834764831845f;
    for (int i = tid; i < KEY_DIM; i += 256) {
        int kh = i >> 7;
        int d  = i & 127;
        size_t o0 = ((size_t)bt * HK + kh) * KD + d;
        qn[o0] = buf[i] * rnorm[kh] * QSCALE;
        kn[o0] = buf[KEY_DIM + i] * rnorm[HK + kh];
    }

#pragma unroll
    for (int it = 0; it < 8; it++) {
        int c2 = 2 * KEY_DIM + tid * 2 + it * 512;
        float4 w0 = *(const float4*)(convw + c2 * 4);
        float4 w1 = *(const float4*)(convw + c2 * 4 + 4);
        float wa0[4] = {w0.x, w0.y, w0.z, w0.w};
        float wa1[4] = {w1.x, w1.y, w1.z, w1.w};
        float a0 = 0.f, a1 = 0.f;
#pragma unroll
        for (int j = 0; j < 4; j++) {
            int ts = t - 3 + j;
            if (ts >= 0) {
                __half2 hv = *(const __half2*)(qkvz +
                    ((size_t)b * TT + ts) * QKVZ_S + c2);
                float2 f = __half22float2(hv);
                a0 += wa0[j] * f.x;
                a1 += wa1[j] * f.y;
            }
        }
        int cv = c2 - 2 * KEY_DIM;
        vv[(size_t)bt * VALUE_DIM + cv] = silu_f(a0);
        vv[(size_t)bt * VALUE_DIM + cv + 1] = silu_f(a1);
    }

    if (tid < HV) {
        float bg = __half2float(qkvz[(size_t)bt * QKVZ_S + 12288 + tid]);
        float a  = __half2float(qkvz[(size_t)bt * QKVZ_S + 12320 + tid]) + dtb[tid];
        float beta = 1.f / (1.f + __expf(-bg));
        float sp = (a > 20.f) ? a : log1pf(__expf(a));
        float eg = __expf(-__expf(Alog[tid]) * sp);
        gb[(size_t)bt * HV + tid] = make_float2(eg, beta);
    }
}

// ---------------------------------------------------------------------------
// Gated delta-rule scan v8: f32 operands (R13 layout), 16 warps, deferred
// output reduction (o shfls of step t overlap step t+1's compute).
// 128 blocks = (b, h, vhalf); 512 threads. Thread tile 16k x 1v.
// ---------------------------------------------------------------------------
struct ScanPB {
    ulonglong2 k[4];
    ulonglong2 q[4];
    float v;
    float eg, beta;
};

__device__ __forceinline__ void scan_pf(
    ScanPB& pb, int t, int b, int kh, int h, int kgofs, int vofs,
    const float* __restrict__ qn, const float* __restrict__ kn,
    const float* __restrict__ vv, const float2* __restrict__ gb)
{
    int tc = t < TT ? t : TT - 1;
    size_t rowk = (((size_t)b * TT + tc) * HK + kh) * (size_t)KD + kgofs;
    const ulonglong2* kp = (const ulonglong2*)(kn + rowk);
    const ulonglong2* qp = (const ulonglong2*)(qn + rowk);
#pragma unroll
    for (int m = 0; m < 4; m++) { pb.k[m] = kp[m]; pb.q[m] = qp[m]; }
    size_t rowv = (((size_t)b * TT + tc) * HV + h) * (size_t)VD + vofs;
    pb.v = vv[rowv];
    float2 g2 = gb[((size_t)b * TT + tc) * HV + h];
    pb.eg = g2.x;
    pb.beta = g2.y;
}

// pred + delta + state update; returns UNREDUCED per-thread output partial
__device__ __forceinline__ float scan_part(
    ull* __restrict__ S2, const ScanPB& pb)
{
    ull eg2 = pack2(pb.eg, pb.eg);
    ull p2a = 0ull, p2b = 0ull;
#pragma unroll
    for (int m = 0; m < 4; m++) {
        ull s0 = fmul2(S2[2 * m], eg2);
        S2[2 * m] = s0;
        p2a = ffma2(pb.k[m].x, s0, p2a);
        ull s1 = fmul2(S2[2 * m + 1], eg2);
        S2[2 * m + 1] = s1;
        p2b = ffma2(pb.k[m].y, s1, p2b);
    }
    float p = (lo2(p2a) + hi2(p2a)) + (lo2(p2b) + hi2(p2b));
    p += __shfl_xor_sync(0xffffffffu, p, 4);
    p += __shfl_xor_sync(0xffffffffu, p, 8);
    p += __shfl_xor_sync(0xffffffffu, p, 16);
    float d = (pb.v - p) * pb.beta;
    ull d2 = pack2(d, d);
    ull o2a = 0ull, o2b = 0ull;
#pragma unroll
    for (int m = 0; m < 4; m++) {
        ull s0 = ffma2(pb.k[m].x, d2, S2[2 * m]);
        S2[2 * m] = s0;
        o2a = ffma2(pb.q[m].x, s0, o2a);
        ull s1 = ffma2(pb.k[m].y, d2, S2[2 * m + 1]);
        S2[2 * m + 1] = s1;
        o2b = ffma2(pb.q[m].y, s1, o2b);
    }
    return (lo2(o2a) + hi2(o2a)) + (lo2(o2b) + hi2(o2b));
}

// reduce partial across kg and store (deferred)
__device__ __forceinline__ void scan_flush(
    float o, int t, int kg, size_t obase, __half* __restrict__ oo)
{
    o += __shfl_xor_sync(0xffffffffu, o, 4);
    o += __shfl_xor_sync(0xffffffffu, o, 8);
    o += __shfl_xor_sync(0xffffffffu, o, 16);
    if (kg == 0)
        oo[obase + (size_t)t * (HV * VD)] = __float2half(o);
}

__global__ __launch_bounds__(512, 1) void scan_kernel(
    const float* __restrict__ qn, const float* __restrict__ kn,
    const float* __restrict__ vv, const float2* __restrict__ gb,
    __half* __restrict__ oo)
{
    const int bh2 = blockIdx.x;
    const int b = bh2 >> 6;
    const int rem = bh2 & 63;
    const int h = rem >> 1;
    const int vhalf = rem & 1;
    const int kh = h >> 1;
    const int tid = threadIdx.x;
    const int w = tid >> 5;
    const int lane = tid & 31;
    const int kg = lane >> 2;
    const int c = lane & 3;
    const int kgofs = kg * 16;
    const int vofs = vhalf * 64 + w * 4 + c;

    ull S2[8];
#pragma unroll
    for (int i = 0; i < 8; i++) S2[i] = 0ull;

    const size_t obase = (((size_t)b * TT) * HV + h) * (size_t)VD + vofs;

    ScanPB A, B;
    scan_pf(A, 0, b, kh, h, kgofs, vofs, qn, kn, vv, gb);

    for (int t = 0; t < TT; t += 2) {
        scan_pf(B, t + 1, b, kh, h, kgofs, vofs, qn, kn, vv, gb);
        float oA = scan_part(S2, A);
        scan_pf(A, t + 2, b, kh, h, kgofs, vofs, qn, kn, vv, gb);
        float oB = scan_part(S2, B);
        // deferred reductions: overlap with the next iteration's loads/compute
        scan_flush(oA, t, kg, obase, oo);
        scan_flush(oB, t + 1, kg, obase, oo);
    }
}

// ---------------------------------------------------------------------------
// gated rmsnorm (oo f16) -> f16 output for GEMM2's A operand
// ---------------------------------------------------------------------------
__global__ __launch_bounds__(256) void rmsnorm_kernel(
    const __half* __restrict__ oo, const __half* __restrict__ qkvz,
    const float* __restrict__ nw, __half* __restrict__ xout)
{
    const int bt = blockIdx.x;
    const int warp = threadIdx.x >> 5;
    const int lane = threadIdx.x & 31;

    for (int hh = warp; hh < HV; hh += 8) {
        const size_t base = ((size_t)bt * HV + hh) * (size_t)VD;
        const __half* zz = qkvz + (size_t)bt * QKVZ_S + 2 * KEY_DIM + VALUE_DIM
                           + (size_t)hh * VD;
        float xv[4];
        float ss = 0.f;
#pragma unroll
        for (int i = 0; i < 4; i++) {
            int d = lane + 32 * i;
            float z = __half2float(zz[d]);
            float x = __half2float(oo[base + d]) * silu_f(z);
            xv[i] = x;
            ss += x * x;
        }
#pragma unroll
        for (int off = 16; off; off >>= 1)
            ss += __shfl_xor_sync(0xffffffffu, ss, off);
        float r = rsqrtf(ss * (1.f / 128.f) + 1e-6f);
#pragma unroll
        for (int i = 0; i < 4; i++) {
            int d = lane + 32 * i;
            xout[(size_t)bt * VALUE_DIM + hh * VD + d] =
                __float2half(xv[i] * r * (1.f + nw[d]));
        }
    }
}

// ---------------------------------------------------------------------------
// Launch
// ---------------------------------------------------------------------------
extern "C" void kernel_launch(void* const* d_in, const int* in_sizes, int n_in,
                              void* d_out, int out_size)
{
    const float* hs    = (const float*)d_in[0];
    const float* Wqkvz = (const float*)d_in[1];
    const float* Wba   = (const float*)d_in[2];
    const float* convw = (const float*)d_in[3];
    const float* Alog  = (const float*)d_in[4];
    const float* dtb   = (const float*)d_in[5];
    const float* nw    = (const float*)d_in[6];
    const float* Wout  = (const float*)d_in[7];
    float* out = (float*)d_out;

    float *qn, *kn, *vv;
    float2 *gb;
    __half *qkvzh, *ooh, *ah, *w1h, *w2h, *xh;
    cudaGetSymbolAddress((void**)&qkvzh, g_qkvzh);
    cudaGetSymbolAddress((void**)&qn,   g_qn);
    cudaGetSymbolAddress((void**)&kn,   g_kn);
    cudaGetSymbolAddress((void**)&vv,   g_v);
    cudaGetSymbolAddress((void**)&ooh,  g_oh);
    cudaGetSymbolAddress((void**)&gb,   g_gb);
    cudaGetSymbolAddress((void**)&ah,   g_ah);
    cudaGetSymbolAddress((void**)&w1h,  g_w1h);
    cudaGetSymbolAddress((void**)&w2h,  g_w2h);
    cudaGetSymbolAddress((void**)&xh,   g_xh);

    cudaFuncSetAttribute(h_gemm_kernel<__half>,
                         cudaFuncAttributeMaxDynamicSharedMemorySize, GEMM_SMEM);
    cudaFuncSetAttribute(h_gemm_kernel<float>,
                         cudaFuncAttributeMaxDynamicSharedMemorySize, GEMM_SMEM);

    // prep
    convert_h_kernel<<<(BT * DD / 4 + 255) / 256, 256>>>(hs, ah, BT * DD / 4);
    transpose_h_kernel<<<dim3(12288 / 32, DD / 32), 256>>>(Wqkvz, w1h, DD, 12288);
    transpose_ba_kernel<<<dim3(4, 64), 256>>>(Wba, w1h);
    transpose_h_kernel<<<dim3(DD / 32, VALUE_DIM / 32), 256>>>(Wout, w2h, VALUE_DIM, DD);

    // 1) [qkvz | ba] = hs @ [W_qkvz | W_ba | 0]  : [4096,2048]x[2048,12416]
    h_gemm_kernel<__half><<<dim3(QKVZ_S / 128, BT / 128), 256, GEMM_SMEM>>>(
        ah, w1h, qkvzh, BT, QKVZ_S, DD);

    // 2) conv + silu + l2norm + gating
    conv_gate_kernel<<<BT, 256>>>(qkvzh, convw, Alog, dtb, qn, kn, vv, gb);

    // 3) gated delta rule scan (deferred output reduction)
    scan_kernel<<<128, 512>>>(qn, kn, vv, gb, ooh);

    // 4) gated rmsnorm -> f16
    rmsnorm_kernel<<<BT, 256>>>(ooh, qkvzh, nw, xh);

    // 5) out = x @ W_out : [4096,4096]x[4096,2048]
    h_gemm_kernel<float><<<dim3(DD / 128, BT / 128), 256, GEMM_SMEM>>>(
        xh, w2h, out, BT, DD, VALUE_DIM);
}